// round 3
// baseline (speedup 1.0000x reference)
#include <cuda_runtime.h>
#include <cstddef>
#include <cstdint>

// Problem constants: B=2, S=512, H=256, A=128
#define BB 2
#define SS 512
#define HH 256
#define AA 128
#define NT 32          // tiles per batch for the a-prefix
#define TS 16          // rows per tile (NT*TS == SS)

// Scratch (device globals; no allocs allowed)
__device__ float g_s[BB * SS];          // raw scores s[b,j]
__device__ float g_w[BB * SS];          // e_j * am_j
__device__ float g_scale[BB * SS];      // am_i / C_i
__device__ float g_T[BB * NT * HH];     // per-tile sums of w_j * x[b,j,:]

// ---------------------------------------------------------------------------
// Kernel 1: s[b,j] = sum_a query[a] * tanh( sum_h x[b,j,h] * w_a[h,a] )
// 8 rows per block (grid 128), 128 threads.
// Thread = (row-pair p = tid>>5, 4 a-cols c0 = (tid&31)*4).
// Per h: 1 LDG.128 (w4) + 1 LDS.64 (2 rows, broadcast) + 2 mov + 4 f32x2 FMA.
// ---------------------------------------------------------------------------
__global__ __launch_bounds__(128) void k_score(
    const float* __restrict__ x, const float* __restrict__ w_a,
    const float* __restrict__ query)
{
    __shared__ float xsT[HH * 8];     // xsT[h*8 + r], r in 0..7
    const int tid = threadIdx.x;
    const int r0  = blockIdx.x * 8;   // global row (b*S + j) of first row
    const int lane = tid & 31;
    const int p    = tid >> 5;        // row-pair 0..3 (== warp id)

    // load 8 rows (2048 floats) into transposed shared layout
    const float4* xin = reinterpret_cast<const float4*>(x + (size_t)r0 * HH);
#pragma unroll
    for (int it = 0; it < 4; ++it) {
        const int idx = tid + it * 128;     // 0..511 float4 slots
        const int r   = idx & 7;
        const int h4  = idx >> 3;           // 0..63
        const float4 v = xin[r * 64 + h4];
        xsT[(h4 * 4 + 0) * 8 + r] = v.x;
        xsT[(h4 * 4 + 1) * 8 + r] = v.y;
        xsT[(h4 * 4 + 2) * 8 + r] = v.z;
        xsT[(h4 * 4 + 3) * 8 + r] = v.w;
    }
    __syncthreads();

    // accumulators: [row in pair][col-pair]  as packed f32x2
    unsigned long long acc00 = 0, acc01 = 0, acc10 = 0, acc11 = 0;

    const float4* wp = reinterpret_cast<const float4*>(w_a) + lane; // 32 float4 = row
    const float2* xp2 = reinterpret_cast<const float2*>(xsT) + p;   // stride 4 float2/h

#pragma unroll 4
    for (int h = 0; h < HH; ++h) {
        const float4 w4 = wp[h * 32];
        unsigned long long w01, w23;
        asm("mov.b64 %0, {%1, %2};" : "=l"(w01) : "f"(w4.x), "f"(w4.y));
        asm("mov.b64 %0, {%1, %2};" : "=l"(w23) : "f"(w4.z), "f"(w4.w));
        const float2 x2 = xp2[h * 4];
        unsigned long long xd0, xd1;
        asm("mov.b64 %0, {%1, %1};" : "=l"(xd0) : "f"(x2.x));
        asm("mov.b64 %0, {%1, %1};" : "=l"(xd1) : "f"(x2.y));
        asm("fma.rn.f32x2 %0, %1, %2, %0;" : "+l"(acc00) : "l"(xd0), "l"(w01));
        asm("fma.rn.f32x2 %0, %1, %2, %0;" : "+l"(acc01) : "l"(xd0), "l"(w23));
        asm("fma.rn.f32x2 %0, %1, %2, %0;" : "+l"(acc10) : "l"(xd1), "l"(w01));
        asm("fma.rn.f32x2 %0, %1, %2, %0;" : "+l"(acc11) : "l"(xd1), "l"(w23));
    }

    // epilogue: tanh, weight by query, reduce over the 128 a-cols (warp-wide)
    const float4 q4 = reinterpret_cast<const float4*>(query)[lane];
    float v00lo, v00hi, v01lo, v01hi, v10lo, v10hi, v11lo, v11hi;
    asm("mov.b64 {%0, %1}, %2;" : "=f"(v00lo), "=f"(v00hi) : "l"(acc00));
    asm("mov.b64 {%0, %1}, %2;" : "=f"(v01lo), "=f"(v01hi) : "l"(acc01));
    asm("mov.b64 {%0, %1}, %2;" : "=f"(v10lo), "=f"(v10hi) : "l"(acc10));
    asm("mov.b64 {%0, %1}, %2;" : "=f"(v11lo), "=f"(v11hi) : "l"(acc11));

    float s0 = q4.x * tanhf(v00lo) + q4.y * tanhf(v00hi)
             + q4.z * tanhf(v01lo) + q4.w * tanhf(v01hi);
    float s1 = q4.x * tanhf(v10lo) + q4.y * tanhf(v10hi)
             + q4.z * tanhf(v11lo) + q4.w * tanhf(v11hi);
#pragma unroll
    for (int o = 16; o > 0; o >>= 1) {
        s0 += __shfl_down_sync(0xffffffffu, s0, o);
        s1 += __shfl_down_sync(0xffffffffu, s1, o);
    }
    if (lane == 0) {
        g_s[r0 + 2 * p]     = s0;
        g_s[r0 + 2 * p + 1] = s1;
    }
}

// ---------------------------------------------------------------------------
// Kernel 2: per-batch max + exp + inclusive prefix sum (shfl warp scans).
// ---------------------------------------------------------------------------
__global__ __launch_bounds__(512) void k_scan(const int* __restrict__ amask)
{
    const int b = blockIdx.x, tid = threadIdx.x;
    const int lane = tid & 31, wid = tid >> 5;   // 16 warps
    __shared__ float wmax[16], wsum[16];

    const float sv = g_s[b * SS + tid];

    float m = sv;
#pragma unroll
    for (int o = 16; o > 0; o >>= 1) m = fmaxf(m, __shfl_xor_sync(0xffffffffu, m, o));
    if (lane == 0) wmax[wid] = m;
    __syncthreads();
    float M = wmax[0];
#pragma unroll
    for (int k = 1; k < 16; ++k) M = fmaxf(M, wmax[k]);

    const float e = expf(sv - M);

    float sc = e;
#pragma unroll
    for (int o = 1; o < 32; o <<= 1) {
        const float t = __shfl_up_sync(0xffffffffu, sc, o);
        if (lane >= o) sc += t;
    }
    if (lane == 31) wsum[wid] = sc;
    __syncthreads();
    float off = 0.f;
#pragma unroll
    for (int k = 0; k < 16; ++k)
        if (k < wid) off += wsum[k];

    const float C  = sc + off;
    const int   am = amask[b * SS + tid];
    g_w[b * SS + tid]     = am ? e : 0.f;
    g_scale[b * SS + tid] = am ? (1.f / C) : 0.f;
}

// ---------------------------------------------------------------------------
// Kernel 3: grid (64 + NT, B), 256 threads.
//  bx <  64 : write 8 rows of d. Thread keeps its w4 in regs, 4 STG.128.
//  bx >= 64 : tile-sum T[b,t,h] with fully batched loads.
// ---------------------------------------------------------------------------
__global__ __launch_bounds__(256) void k_dwrite(
    const float* __restrict__ x, float* __restrict__ d_out)
{
    const int b = blockIdx.y, tid = threadIdx.x;

    if (blockIdx.x < 64) {
        const int i0   = blockIdx.x * 8;
        const int slot = tid & 127;        // float4 slot: cols j0..j0+3
        const int rp   = tid >> 7;         // 0/1
        const int j0   = slot * 4;
        const float4 w4 = reinterpret_cast<const float4*>(g_w + b * SS)[slot];
        float4* drow = reinterpret_cast<float4*>(d_out + (size_t)(b * SS) * SS) + slot;
#pragma unroll
        for (int pass = 0; pass < 4; ++pass) {
            const int i = i0 + pass * 2 + rp;
            const float sc = g_scale[b * SS + i];
            float4 o;
            o.x = (j0     <= i) ? w4.x * sc : 0.f;
            o.y = (j0 + 1 <= i) ? w4.y * sc : 0.f;
            o.z = (j0 + 2 <= i) ? w4.z * sc : 0.f;
            o.w = (j0 + 3 <= i) ? w4.w * sc : 0.f;
            drow[(size_t)i * 128] = o;
        }
    } else {
        const int t = blockIdx.x - 64;          // 0..NT-1
        __shared__ float ws[TS];
        if (tid < TS) ws[tid] = g_w[b * SS + t * TS + tid];
        __syncthreads();
        const float* xp = x + ((size_t)(b * SS + t * TS)) * HH + tid;
        float xv[TS];
#pragma unroll
        for (int jj = 0; jj < TS; ++jj) xv[jj] = xp[(size_t)jj * HH];
        float acc = 0.f;
#pragma unroll
        for (int jj = 0; jj < TS; ++jj) acc += ws[jj] * xv[jj];
        g_T[(b * NT + t) * HH + tid] = acc;
    }
}

// ---------------------------------------------------------------------------
// Kernel 4: a[b,i,h]. grid (NT, B*2), 128 threads (half of h per block).
// ALL loads unconditional + batched (MLP ~47); only the sum is predicated.
// ---------------------------------------------------------------------------
__global__ __launch_bounds__(128) void k_awrite(
    const float* __restrict__ x, float* __restrict__ a_out)
{
    const int t  = blockIdx.x;
    const int b  = blockIdx.y & 1;
    const int h  = (blockIdx.y >> 1) * 128 + threadIdx.x;
    const int tid = threadIdx.x;

    __shared__ float ws[TS], scs[TS];
    if (tid < TS) {
        ws[tid]  = g_w[b * SS + t * TS + tid];
        scs[tid] = g_scale[b * SS + t * TS + tid];
    }
    __syncthreads();

    // batch-load tile's x values AND all 31 tile totals unconditionally
    const float* xp = x + ((size_t)(b * SS + t * TS)) * HH + h;
    float xv[TS];
#pragma unroll
    for (int jj = 0; jj < TS; ++jj) xv[jj] = xp[(size_t)jj * HH];

    const float* Tp = g_T + (size_t)(b * NT) * HH + h;
    float tv[NT - 1];
#pragma unroll
    for (int tp = 0; tp < NT - 1; ++tp) tv[tp] = Tp[(size_t)tp * HH];

    // predicated tree-free sum of previous tiles (loads already in flight)
    float base = 0.f;
#pragma unroll
    for (int tp = 0; tp < NT - 1; ++tp) base += (tp < t) ? tv[tp] : 0.f;

    float* ap = a_out + ((size_t)(b * SS + t * TS)) * HH + h;
    float acc = base;
#pragma unroll
    for (int jj = 0; jj < TS; ++jj) {
        acc += ws[jj] * xv[jj];
        ap[(size_t)jj * HH] = acc * scs[jj];
    }
}

// ---------------------------------------------------------------------------
extern "C" void kernel_launch(void* const* d_in, const int* in_sizes, int n_in,
                              void* d_out, int out_size)
{
    const float* x     = (const float*)d_in[0];   // (B,S,H)
    const int*   amask = (const int*)  d_in[1];   // (B,S)
    const float* w_a   = (const float*)d_in[2];   // (H,A)
    const float* query = (const float*)d_in[3];   // (A,)

    float* out   = (float*)d_out;
    float* a_out = out;                                // (B,S,H) first
    float* dd    = out + (size_t)BB * SS * HH;         // (B,S,S) second

    k_score<<<(BB * SS) / 8, 128>>>(x, w_a, query);
    k_scan<<<BB, SS>>>(amask);
    k_dwrite<<<dim3(64 + NT, BB), 256>>>(x, dd);
    k_awrite<<<dim3(NT, BB * 2), 128>>>(x, a_out);
}

// round 4
// speedup vs baseline: 2.2229x; 2.2229x over previous
#include <cuda_runtime.h>
#include <cstddef>
#include <cstdint>

// Problem constants: B=2, S=512, H=256, A=128
#define BB 2
#define SS 512
#define HH 256
#define AA 128
#define NT 32          // tiles per batch for the a-prefix
#define TS 16          // rows per tile (NT*TS == SS)

// Scratch (device globals; no allocs allowed)
__device__ float g_s[BB * SS];          // raw scores s[b,j]
__device__ float g_w[BB * SS];          // e_j * am_j
__device__ float g_scale[BB * SS];      // am_i / C_i
__device__ float g_T[BB * NT * HH];     // per-tile sums of w_j * x[b,j,:]

// ---------------------------------------------------------------------------
// Kernel 1: s[b,j] = sum_a query[a] * tanh( sum_h x[b,j,h] * w_a[h,a] )
// grid 128 (8 rows/block), block 512 (16 warps).
// warp = (row-pair p = wid&3, h-group g = wid>>2, 64 h each).
// w loads: two-deep double-buffered asm-volatile LDG.128 (forced MLP=8).
// ---------------------------------------------------------------------------
__global__ __launch_bounds__(512) void k_score(
    const float* __restrict__ x, const float* __restrict__ w_a,
    const float* __restrict__ query)
{
    __shared__ float xsT[HH * 8];            // xsT[h*8 + r]
    __shared__ float sred[8][5][AA];         // [row][g(pad 5)][col]  (20 KB)
    const int tid  = threadIdx.x;
    const int lane = tid & 31;
    const int wid  = tid >> 5;
    const int p    = wid & 3;
    const int g    = wid >> 2;
    const int r0   = blockIdx.x * 8;

    // stage 8 rows of x transposed
    {
        const int r  = tid & 7;
        const int h4 = tid >> 3;             // 0..63
        const float4 v =
            reinterpret_cast<const float4*>(x + (size_t)r0 * HH)[r * 64 + h4];
        xsT[(h4 * 4 + 0) * 8 + r] = v.x;
        xsT[(h4 * 4 + 1) * 8 + r] = v.y;
        xsT[(h4 * 4 + 2) * 8 + r] = v.z;
        xsT[(h4 * 4 + 3) * 8 + r] = v.w;
    }
    __syncthreads();

    float a00=0.f,a01=0.f,a02=0.f,a03=0.f,a10=0.f,a11=0.f,a12=0.f,a13=0.f;
    const int h0 = g * 64;
    const float* wp = w_a + (size_t)h0 * AA + lane * 4;
    const float* xp = xsT + h0 * 8 + 2 * p;

    float4 bufA[8], bufB[8];

#define LDW(dst, off)                                                        \
    asm volatile("ld.global.nc.v4.f32 {%0,%1,%2,%3}, [%4];"                  \
        : "=f"((dst).x), "=f"((dst).y), "=f"((dst).z), "=f"((dst).w)         \
        : "l"(wp + (size_t)(off) * AA))

#define COMPUTE(buf, c)                                                      \
    _Pragma("unroll")                                                        \
    for (int u = 0; u < 8; ++u) {                                            \
        const float2 x2 =                                                    \
            *reinterpret_cast<const float2*>(xp + (size_t)((c) * 8 + u) * 8);\
        const float4 w4 = (buf)[u];                                          \
        a00 += x2.x * w4.x; a01 += x2.x * w4.y;                              \
        a02 += x2.x * w4.z; a03 += x2.x * w4.w;                              \
        a10 += x2.y * w4.x; a11 += x2.y * w4.y;                              \
        a12 += x2.y * w4.z; a13 += x2.y * w4.w;                              \
    }

    // prologue: chunk 0 into A
#pragma unroll
    for (int u = 0; u < 8; ++u) LDW(bufA[u], u);

#pragma unroll
    for (int c = 0; c < 8; c += 2) {
        if (c + 1 < 8) {
#pragma unroll
            for (int u = 0; u < 8; ++u) LDW(bufB[u], (c + 1) * 8 + u);
        }
        COMPUTE(bufA, c);
        if (c + 1 < 8) {
            if (c + 2 < 8) {
#pragma unroll
                for (int u = 0; u < 8; ++u) LDW(bufA[u], (c + 2) * 8 + u);
            }
            COMPUTE(bufB, c + 1);
        }
    }
#undef LDW
#undef COMPUTE

    // stash partials (STS.128, conflict-free: 16B stride per lane)
    *reinterpret_cast<float4*>(&sred[2 * p + 0][g][lane * 4]) =
        make_float4(a00, a01, a02, a03);
    *reinterpret_cast<float4*>(&sred[2 * p + 1][g][lane * 4]) =
        make_float4(a10, a11, a12, a13);
    __syncthreads();

    // warps 0..7: row = wid; combine 4 h-groups, tanh, dot q, warp-reduce
    if (wid < 8) {
        const float4 q4 = reinterpret_cast<const float4*>(query)[lane];
        const float4 v0 = *reinterpret_cast<const float4*>(&sred[wid][0][lane * 4]);
        const float4 v1 = *reinterpret_cast<const float4*>(&sred[wid][1][lane * 4]);
        const float4 v2 = *reinterpret_cast<const float4*>(&sred[wid][2][lane * 4]);
        const float4 v3 = *reinterpret_cast<const float4*>(&sred[wid][3][lane * 4]);
        const float c0 = v0.x + v1.x + v2.x + v3.x;
        const float c1 = v0.y + v1.y + v2.y + v3.y;
        const float c2 = v0.z + v1.z + v2.z + v3.z;
        const float c3 = v0.w + v1.w + v2.w + v3.w;
        float s = q4.x * tanhf(c0) + q4.y * tanhf(c1)
                + q4.z * tanhf(c2) + q4.w * tanhf(c3);
#pragma unroll
        for (int o = 16; o > 0; o >>= 1) s += __shfl_down_sync(0xffffffffu, s, o);
        if (lane == 0) g_s[r0 + wid] = s;
    }
}

// ---------------------------------------------------------------------------
// Kernel 2: per-batch max + exp + inclusive prefix sum (shfl warp scans).
// ---------------------------------------------------------------------------
__global__ __launch_bounds__(512) void k_scan(const int* __restrict__ amask)
{
    const int b = blockIdx.x, tid = threadIdx.x;
    const int lane = tid & 31, wid = tid >> 5;   // 16 warps
    __shared__ float wmax[16], wsum[16];

    const float sv = g_s[b * SS + tid];

    float m = sv;
#pragma unroll
    for (int o = 16; o > 0; o >>= 1) m = fmaxf(m, __shfl_xor_sync(0xffffffffu, m, o));
    if (lane == 0) wmax[wid] = m;
    __syncthreads();
    float M = wmax[0];
#pragma unroll
    for (int k = 1; k < 16; ++k) M = fmaxf(M, wmax[k]);

    const float e = expf(sv - M);

    float sc = e;
#pragma unroll
    for (int o = 1; o < 32; o <<= 1) {
        const float t = __shfl_up_sync(0xffffffffu, sc, o);
        if (lane >= o) sc += t;
    }
    if (lane == 31) wsum[wid] = sc;
    __syncthreads();
    float off = 0.f;
#pragma unroll
    for (int k = 0; k < 16; ++k)
        if (k < wid) off += wsum[k];

    const float C  = sc + off;
    const int   am = amask[b * SS + tid];
    g_w[b * SS + tid]     = am ? e : 0.f;
    g_scale[b * SS + tid] = am ? (1.f / C) : 0.f;
}

// ---------------------------------------------------------------------------
// Kernel 3: grid (SS + NT, B), 256 threads.
//  bx < SS : write one d row (float2 stores).
//  else    : tile-sum T[b,t,h], loads forced-batched via asm volatile.
// ---------------------------------------------------------------------------
__global__ __launch_bounds__(256) void k_dwrite(
    const float* __restrict__ x, float* __restrict__ d_out)
{
    const int b = blockIdx.y, tid = threadIdx.x;

    if (blockIdx.x < SS) {
        const int i  = blockIdx.x;
        const float sc = g_scale[b * SS + i];
        const float2 w2 = reinterpret_cast<const float2*>(g_w + b * SS)[tid];
        const int j0 = tid * 2;
        float2 o;
        o.x = (j0     <= i) ? w2.x * sc : 0.f;
        o.y = (j0 + 1 <= i) ? w2.y * sc : 0.f;
        reinterpret_cast<float2*>(d_out + (size_t)(b * SS + i) * SS)[tid] = o;
    } else {
        const int t = blockIdx.x - SS;          // 0..NT-1
        __shared__ float ws[TS];
        if (tid < TS) ws[tid] = g_w[b * SS + t * TS + tid];
        __syncthreads();
        const float* xp = x + ((size_t)(b * SS + t * TS)) * HH + tid;
        float xv[TS];
#pragma unroll
        for (int jj = 0; jj < TS; ++jj)
            asm volatile("ld.global.nc.f32 %0, [%1];"
                         : "=f"(xv[jj]) : "l"(xp + (size_t)jj * HH));
        float s01 = ws[0]*xv[0], s23 = ws[2]*xv[2], s45 = ws[4]*xv[4], s67 = ws[6]*xv[6];
        s01 += ws[1]*xv[1]; s23 += ws[3]*xv[3]; s45 += ws[5]*xv[5]; s67 += ws[7]*xv[7];
        float t01 = ws[8]*xv[8], t23 = ws[10]*xv[10], t45 = ws[12]*xv[12], t67 = ws[14]*xv[14];
        t01 += ws[9]*xv[9]; t23 += ws[11]*xv[11]; t45 += ws[13]*xv[13]; t67 += ws[15]*xv[15];
        const float acc = ((s01 + s23) + (s45 + s67)) + ((t01 + t23) + (t45 + t67));
        g_T[(b * NT + t) * HH + tid] = acc;
    }
}

// ---------------------------------------------------------------------------
// Kernel 4: a[b,i,h]. grid (NT, B*2), 128 threads (half of h per block).
// All 47 loads forced-batched via asm volatile; predicated SEL + tree sum.
// ---------------------------------------------------------------------------
__global__ __launch_bounds__(128) void k_awrite(
    const float* __restrict__ x, float* __restrict__ a_out)
{
    const int t  = blockIdx.x;
    const int b  = blockIdx.y & 1;
    const int h  = (blockIdx.y >> 1) * 128 + threadIdx.x;
    const int tid = threadIdx.x;

    __shared__ float ws[TS], scs[TS];
    if (tid < TS) {
        ws[tid]  = g_w[b * SS + t * TS + tid];
        scs[tid] = g_scale[b * SS + t * TS + tid];
    }
    __syncthreads();

    const float* xp = x   + ((size_t)(b * SS + t * TS)) * HH + h;
    const float* Tp = g_T + (size_t)(b * NT) * HH + h;

    float xv[TS];
    float tv[NT];       // tv[NT-1] unused slot keeps tree sizes power-of-2
#pragma unroll
    for (int jj = 0; jj < TS; ++jj)
        asm volatile("ld.global.nc.f32 %0, [%1];"
                     : "=f"(xv[jj]) : "l"(xp + (size_t)jj * HH));
#pragma unroll
    for (int tp = 0; tp < NT - 1; ++tp)
        asm volatile("ld.global.nc.f32 %0, [%1];"
                     : "=f"(tv[tp]) : "l"(Tp + (size_t)tp * HH));
    tv[NT - 1] = 0.f;

    // predicated select (t uniform per block), then pairwise tree sum
#pragma unroll
    for (int tp = 0; tp < NT - 1; ++tp) tv[tp] = (tp < t) ? tv[tp] : 0.f;
#pragma unroll
    for (int s = NT / 2; s >= 1; s >>= 1) {
#pragma unroll
        for (int k = 0; k < s; ++k) tv[k] += tv[k + s];
    }
    float acc = tv[0];

    float* ap = a_out + ((size_t)(b * SS + t * TS)) * HH + h;
#pragma unroll
    for (int jj = 0; jj < TS; ++jj) {
        acc += ws[jj] * xv[jj];
        ap[(size_t)jj * HH] = acc * scs[jj];
    }
}

// ---------------------------------------------------------------------------
extern "C" void kernel_launch(void* const* d_in, const int* in_sizes, int n_in,
                              void* d_out, int out_size)
{
    const float* x     = (const float*)d_in[0];   // (B,S,H)
    const int*   amask = (const int*)  d_in[1];   // (B,S)
    const float* w_a   = (const float*)d_in[2];   // (H,A)
    const float* query = (const float*)d_in[3];   // (A,)

    float* out   = (float*)d_out;
    float* a_out = out;                                // (B,S,H) first
    float* dd    = out + (size_t)BB * SS * HH;         // (B,S,S) second

    k_score<<<(BB * SS) / 8, 512>>>(x, w_a, query);
    k_scan<<<BB, SS>>>(amask);
    k_dwrite<<<dim3(SS + NT, BB), 256>>>(x, dd);
    k_awrite<<<dim3(NT, BB * 2), 128>>>(x, a_out);
}